// round 13
// baseline (speedup 1.0000x reference)
#include <cuda_runtime.h>
#include <cstdint>

#define NQ 32768
#define RELW 36

// rel scratch: [q][36] = relH[0..15], relW[16..31], relT[32..35]
__device__ float g_rel[NQ * RELW];

// ---------------------------------------------------------------------------
// Kernel 1: rel GEMM, scalar fp32.  P[64q x 72c] = Q @ Ecat^T per block.
// Ecat = [H(31)|W(31)|T(7)|0(3)].  512 blocks x 288 threads (9 warps).
// Warp tc owns cols tc*8..tc*8+7 (ev loads = warp broadcast).
// Lane tq owns queries {tq, tq+32} (qv LDS: 32 consecutive floats = 1 phase).
// lb(288,3): 3 blocks/SM -> 6.75 warps/SMSP, 1.15 waves. R11 evidence says
// rel runs at ~32% FFMA peak with clean smem -> latency/parallelism-bound.
// ---------------------------------------------------------------------------
#define QF 65    // sQf row stride in floats: STS banks (65k+q)%32=(k+q)%32 distinct
#define EF 73    // sEf row stride: (73k+c)%32=(9k+c)%32, gcd(9,32)=1 distinct
#define PP 73    // sP row stride
// smem: sQf [64][65] + sEf [64][73] = 16,640 + 18,688 = 35,328 B (sP fits inside)
#define RELSMEM (64 * QF * 4 + 64 * EF * 4)

__global__ __launch_bounds__(288, 3)
void rel_gemm(const float* __restrict__ query,
              const float* __restrict__ Hemb,   // [31,64]
              const float* __restrict__ Wemb,   // [31,64]
              const float* __restrict__ Temb)   // [7,64]
{
    extern __shared__ float smf[];
    float* sQf = smf;             // [64][QF]  sQf[k][q]
    float* sEf = smf + 64 * QF;   // [64][EF]  sEf[k][c]

    const int tid   = threadIdx.x;
    const int qbase = blockIdx.x * 64;

    // stage Q transposed to k-major (coalesced gmem reads, conflict-free STS)
    const float* qsrc = query + (size_t)qbase * 64;
    for (int i = tid; i < 64 * 64; i += 288) {
        int q = i >> 6, k = i & 63;
        sQf[k * QF + q] = qsrc[i];
    }
    // stage Ecat k-major
    for (int i = tid; i < 72 * 64; i += 288) {
        int c = i >> 6, k = i & 63;
        float v = 0.f;
        if (c < 31)      v = Hemb[c * 64 + k];
        else if (c < 62) v = Wemb[(c - 31) * 64 + k];
        else if (c < 69) v = Temb[(c - 62) * 64 + k];
        sEf[k * EF + c] = v;
    }
    __syncthreads();

    const int tq = tid & 31;    // lane -> queries tq, tq+32
    const int tc = tid >> 5;    // warp -> cols tc*8 .. tc*8+7

    float acc[2][8];
    #pragma unroll
    for (int i = 0; i < 2; i++)
        #pragma unroll
        for (int j = 0; j < 8; j++) acc[i][j] = 0.f;

    #pragma unroll 2
    for (int k = 0; k < 64; k++) {
        float qv[2], ev[8];
        qv[0] = sQf[k * QF + tq];
        qv[1] = sQf[k * QF + tq + 32];
        #pragma unroll
        for (int j = 0; j < 8; j++) ev[j] = sEf[k * EF + tc * 8 + j];
        #pragma unroll
        for (int i = 0; i < 2; i++)
            #pragma unroll
            for (int j = 0; j < 8; j++) acc[i][j] = fmaf(qv[i], ev[j], acc[i][j]);
    }

    // --- epilogue stage A: acc -> smem P matrix (reuse staging smem)
    __syncthreads();
    float* sP = smf;                        // [64][PP]
    #pragma unroll
    for (int i = 0; i < 2; i++)
        #pragma unroll
        for (int j = 0; j < 8; j++)
            sP[(tq + 32 * i) * PP + tc * 8 + j] = acc[i][j];
    __syncthreads();

    // --- epilogue stage B: branchless coalesced scatter (every slot valid)
    float* relout = g_rel + (size_t)qbase * RELW;
    for (int e = tid; e < 64 * RELW; e += 288) {
        int ql = e / RELW;
        int s  = e - ql * RELW;
        int q  = qbase + ql;
        int c;
        if (s < 16)      c = ((q >> 4) & 15) + 15 - s;            // H: h+15-kh
        else if (s < 32) c = 31 + (q & 15) + 15 - (s - 16);       // W: 31 + w+15-kw
        else             c = 62 + ((q >> 8) & 3) + 3 - (s - 32);  // T: 62 + t+3-kt
        relout[e] = sP[ql * PP + c];
    }
}

// ---------------------------------------------------------------------------
// Kernel 2: pure stream — exact R2 version (proven 38.8us @ 72% DRAM).
// ---------------------------------------------------------------------------
#define QW 16
#define SRS 40

__global__ __launch_bounds__(256)
void stream_kernel(const float* __restrict__ scores,
                   float* __restrict__ out)
{
    __shared__ float sRel[QW][SRS];

    const int bid = blockIdx.x;
    const int tid = threadIdx.x;
    const int qbase = (bid >> 6) * 1024 + ((bid >> 4) & 3) * 256 + (bid & 15) * 16;

    const float* relsrc = g_rel + (size_t)qbase * RELW;
    for (int i = tid; i < QW * RELW; i += 256) {
        int w = i / RELW;
        sRel[w][i - w * RELW] = relsrc[i];
    }
    __syncthreads();

    const int kt  = tid >> 6;
    const int kh  = (tid >> 2) & 15;
    const int kw4 = (tid & 3) << 2;

    const size_t rowbase = (size_t)qbase * 1024;
    const float4* sc4 = (const float4*)(scores + rowbase);
    float4*       ot4 = (float4*)(out + rowbase);

    #pragma unroll 8
    for (int w = 0; w < QW; w++) {
        int v = (w << 8) + tid;
        float4 s = sc4[v];
        float base = sRel[w][kh] + sRel[w][32 + kt];
        float4 rw = *(const float4*)&sRel[w][16 + kw4];
        s.x += base + rw.x;
        s.y += base + rw.y;
        s.z += base + rw.z;
        s.w += base + rw.w;
        ot4[v] = s;
    }
}

extern "C" void kernel_launch(void* const* d_in, const int* in_sizes, int n_in,
                              void* d_out, int out_size) {
    const float* query  = (const float*)d_in[0];
    const float* scores = (const float*)d_in[1];
    const float* Hemb   = (const float*)d_in[2];
    const float* Wemb   = (const float*)d_in[3];
    const float* Temb   = (const float*)d_in[4];
    float* out = (float*)d_out;

    // Launch pattern [rel, stream, rel]: period 3 => ncu's "-s 5 -c 1"
    // (profiles launch #6) lands on rel_gemm instead of always stream.
    // The trailing rel is deterministic dead work — diagnostic cost only.
    rel_gemm<<<512, 288, RELSMEM>>>(query, Hemb, Wemb, Temb);
    stream_kernel<<<2048, 256>>>(scores, out);
    rel_gemm<<<512, 288, RELSMEM>>>(query, Hemb, Wemb, Temb);
}

// round 14
// speedup vs baseline: 1.3785x; 1.3785x over previous
#include <cuda_runtime.h>
#include <cstdint>

#define NQ 32768
#define RELW 36

// rel scratch: [q][36] = relH[0..15], relW[16..31], relT[32..35]
__device__ float g_rel[NQ * RELW];

// ---------------------------------------------------------------------------
// Kernel 1: rel GEMM, float4 q-major.  P[64q x 72c] = Q @ Ecat^T per block.
// Ecat = [H(31)|W(31)|T(7)|0(3)].  512 blocks x 256 threads (8 warps).
// Warp tc owns cols tc*9..tc*9+8 (ev LDS.128 = warp broadcast, free).
// Lane tq owns queries {tq, tq+32}; qv LDS.128 row stride 17 float4 ->
// per-phase banks 4l..4l+3, conflict-free.
// Per k4 iter: 11 LDS.128 feed 72 FFMA (R13 fix: old code did 10 LDS / 16 FFMA
// and was crossbar/LDS-issue bound at 16.6% fma).
// ---------------------------------------------------------------------------
#define QS 17    // sQ4 row stride in float4
#define ES 17    // sE4 row stride in float4
#define PP 73    // sP row stride in floats
// smem: sQ4 [64][17] f4 + sE4 [72][17] f4 = 17,408 + 19,584 = 36,992 B
#define RELSMEM (64 * QS * 16 + 72 * ES * 16)

__global__ __launch_bounds__(256, 3)
void rel_gemm(const float* __restrict__ query,
              const float* __restrict__ Hemb,   // [31,64]
              const float* __restrict__ Wemb,   // [31,64]
              const float* __restrict__ Temb)   // [7,64]
{
    extern __shared__ float4 sm4[];
    float4* sQ4 = sm4;             // [64][QS]  sQ4[q][k4]
    float4* sE4 = sm4 + 64 * QS;   // [72][ES]  sE4[c][k4]

    const int tid   = threadIdx.x;
    const int qbase = blockIdx.x * 64;

    // stage Q q-major (coalesced float4 gmem loads)
    const float4* qsrc = (const float4*)(query + (size_t)qbase * 64);
    for (int i = tid; i < 64 * 16; i += 256) {
        int q = i >> 4, k4 = i & 15;
        sQ4[q * QS + k4] = qsrc[i];
    }
    // stage Ecat c-major (72 cols: H 0..30, W 31..61, T 62..68, zero 69..71)
    for (int i = tid; i < 72 * 16; i += 256) {
        int c = i >> 4, k4 = i & 15;
        float4 v = make_float4(0.f, 0.f, 0.f, 0.f);
        if (c < 31)      v = ((const float4*)Hemb)[c * 16 + k4];
        else if (c < 62) v = ((const float4*)Wemb)[(c - 31) * 16 + k4];
        else if (c < 69) v = ((const float4*)Temb)[(c - 62) * 16 + k4];
        sE4[c * ES + k4] = v;
    }
    __syncthreads();

    const int tq = tid & 31;    // lane -> queries tq, tq+32
    const int tc = tid >> 5;    // warp -> cols tc*9 .. tc*9+8

    float acc[2][9];
    #pragma unroll
    for (int i = 0; i < 2; i++)
        #pragma unroll
        for (int j = 0; j < 9; j++) acc[i][j] = 0.f;

    #pragma unroll 1
    for (int k4 = 0; k4 < 16; k4++) {
        float4 qv0 = sQ4[tq * QS + k4];
        float4 qv1 = sQ4[(tq + 32) * QS + k4];
        #pragma unroll
        for (int j = 0; j < 9; j++) {
            float4 e = sE4[(tc * 9 + j) * ES + k4];
            acc[0][j] = fmaf(qv0.x, e.x, fmaf(qv0.y, e.y,
                        fmaf(qv0.z, e.z, fmaf(qv0.w, e.w, acc[0][j]))));
            acc[1][j] = fmaf(qv1.x, e.x, fmaf(qv1.y, e.y,
                        fmaf(qv1.z, e.z, fmaf(qv1.w, e.w, acc[1][j]))));
        }
    }

    // --- epilogue stage A: acc -> smem P matrix (reuse staging smem)
    __syncthreads();
    float* sP = (float*)sm4;                // [64][PP]
    #pragma unroll
    for (int i = 0; i < 2; i++)
        #pragma unroll
        for (int j = 0; j < 9; j++)
            sP[(tq + 32 * i) * PP + tc * 9 + j] = acc[i][j];
    __syncthreads();

    // --- epilogue stage B: branchless coalesced scatter (every slot valid)
    float* relout = g_rel + (size_t)qbase * RELW;
    for (int e = tid; e < 64 * RELW; e += 256) {
        int ql = e / RELW;
        int s  = e - ql * RELW;
        int q  = qbase + ql;
        int c;
        if (s < 16)      c = ((q >> 4) & 15) + 15 - s;            // H: h+15-kh
        else if (s < 32) c = 31 + (q & 15) + 15 - (s - 16);       // W: 31 + w+15-kw
        else             c = 62 + ((q >> 8) & 3) + 3 - (s - 32);  // T: 62 + t+3-kt
        relout[e] = sP[ql * PP + c];
    }
}

// ---------------------------------------------------------------------------
// Kernel 2: pure stream — exact R2 version (proven 38.8us @ 72% DRAM).
// ---------------------------------------------------------------------------
#define QW 16
#define SRS 40

__global__ __launch_bounds__(256)
void stream_kernel(const float* __restrict__ scores,
                   float* __restrict__ out)
{
    __shared__ float sRel[QW][SRS];

    const int bid = blockIdx.x;
    const int tid = threadIdx.x;
    const int qbase = (bid >> 6) * 1024 + ((bid >> 4) & 3) * 256 + (bid & 15) * 16;

    const float* relsrc = g_rel + (size_t)qbase * RELW;
    for (int i = tid; i < QW * RELW; i += 256) {
        int w = i / RELW;
        sRel[w][i - w * RELW] = relsrc[i];
    }
    __syncthreads();

    const int kt  = tid >> 6;
    const int kh  = (tid >> 2) & 15;
    const int kw4 = (tid & 3) << 2;

    const size_t rowbase = (size_t)qbase * 1024;
    const float4* sc4 = (const float4*)(scores + rowbase);
    float4*       ot4 = (float4*)(out + rowbase);

    #pragma unroll 8
    for (int w = 0; w < QW; w++) {
        int v = (w << 8) + tid;
        float4 s = sc4[v];
        float base = sRel[w][kh] + sRel[w][32 + kt];
        float4 rw = *(const float4*)&sRel[w][16 + kw4];
        s.x += base + rw.x;
        s.y += base + rw.y;
        s.z += base + rw.z;
        s.w += base + rw.w;
        ot4[v] = s;
    }
}

extern "C" void kernel_launch(void* const* d_in, const int* in_sizes, int n_in,
                              void* d_out, int out_size) {
    const float* query  = (const float*)d_in[0];
    const float* scores = (const float*)d_in[1];
    const float* Hemb   = (const float*)d_in[2];
    const float* Wemb   = (const float*)d_in[3];
    const float* Temb   = (const float*)d_in[4];
    float* out = (float*)d_out;

    rel_gemm<<<512, 256, RELSMEM>>>(query, Hemb, Wemb, Temb);
    stream_kernel<<<2048, 256>>>(scores, out);
}